// round 16
// baseline (speedup 1.0000x reference)
#include <cuda_runtime.h>
#include <cuda_fp16.h>
#include <cstdint>

#define NROWS 65536
#define DDIM  256
#define KCODES 1024
#define GAP_T 0.05f   // fp16 single-term: score-diff err sigma ~3.7e-3 -> 13.5-sigma guard
#define SSTR 132      // smem row stride in 32-bit words (128 + 4 pad)
#define CN 64         // codes per W chunk (single-buffered)
#define BM 64         // rows per CTA
#define BUFW (CN * SSTR)

// ---------------- device globals ----------------
__device__ int    g_hist[KCODES];
__device__ double g_commit;
__device__ double g_div;
__device__ float  g_halfnorm[KCODES];
__device__ float  g_invnorm[KCODES];
__device__ float  g_ne[KCODES];
__device__ float  g_Wt[DDIM * KCODES];
__device__ uint32_t g_Whx[KCODES * 128];   // fp16x2-packed W
__device__ int    g_idx[NROWS];
__device__ int    g_flagrows[NROWS];
__device__ int    g_nflag;
__device__ unsigned long long g_best[NROWS];

// ---------------- helpers ----------------
__device__ __forceinline__ unsigned f2o(float f) {
    unsigned b = __float_as_uint(f);
    return (b & 0x80000000u) ? ~b : (b | 0x80000000u);
}
__device__ __forceinline__ float o2f(unsigned u) {
    return (u & 0x80000000u) ? __uint_as_float(u ^ 0x80000000u) : __uint_as_float(~u);
}
__device__ __forceinline__ uint32_t smem_u32(const void* p) {
    uint32_t a;
    asm("{ .reg .u64 t; cvta.to.shared.u64 t, %1; cvt.u32.u64 %0, t; }" : "=r"(a) : "l"(p));
    return a;
}
__device__ __forceinline__ void cpa16(uint32_t dst, const void* src) {
    asm volatile("cp.async.cg.shared.global [%0], [%1], 16;" :: "r"(dst), "l"(src));
}
__device__ __forceinline__ void cpa_commit() {
    asm volatile("cp.async.commit_group;" ::: "memory");
}
__device__ __forceinline__ void cpa_wait0() {
    asm volatile("cp.async.wait_group 0;" ::: "memory");
}
__device__ __forceinline__ void ldsm_x4(uint32_t& r0, uint32_t& r1, uint32_t& r2, uint32_t& r3,
                                        uint32_t addr) {
    asm volatile("ldmatrix.sync.aligned.m8n8.x4.shared.b16 {%0,%1,%2,%3}, [%4];"
        : "=r"(r0), "=r"(r1), "=r"(r2), "=r"(r3) : "r"(addr));
}

__device__ __forceinline__ void mma_f16(float* c, const uint32_t* a, const uint32_t* b) {
    asm volatile(
        "mma.sync.aligned.m16n8k16.row.col.f32.f16.f16.f32 "
        "{%0,%1,%2,%3}, {%4,%5,%6,%7}, {%8,%9}, {%0,%1,%2,%3};"
        : "+f"(c[0]), "+f"(c[1]), "+f"(c[2]), "+f"(c[3])
        : "r"(a[0]), "r"(a[1]), "r"(a[2]), "r"(a[3]), "r"(b[0]), "r"(b[1]));
}

__device__ __forceinline__ uint32_t pack_h16x2(float lo, float hi) {
    __half2 t;
    t.x = __float2half_rn(lo);
    t.y = __float2half_rn(hi);
    return *(uint32_t*)&t;
}

// ---------------- small kernels ----------------
// coalesced tiled transpose: g_Wt[j][k] = W[k][j]
__global__ void vq_tr(const float* __restrict__ W) {
    __shared__ float ts[32][33];
    const int tid = threadIdx.x;          // 256 = 32x8
    const int tx = tid & 31, ty = tid >> 5;
    const int kb = (blockIdx.x & 31) * 32;     // 32 k-tiles
    const int jb = (blockIdx.x >> 5) * 32;     // 8 j-tiles
    #pragma unroll
    for (int dy = 0; dy < 4; dy++) {
        int k = kb + ty + 8 * dy;
        ts[ty + 8 * dy][tx] = W[(size_t)k * DDIM + jb + tx];
    }
    __syncthreads();
    #pragma unroll
    for (int dy = 0; dy < 4; dy++) {
        int j = jb + ty + 8 * dy;
        g_Wt[(size_t)j * KCODES + kb + tx] = ts[tx][ty + 8 * dy];
    }
}

// contracted XLA-emulated ||e||^2 + halfnorm/invnorm + packed fp16 W
__global__ void vq_pre(const float* __restrict__ W) {
    int k = blockIdx.x * 8 + (threadIdx.x >> 5);
    int lane = threadIdx.x & 31;
    float p = 0.f;
    #pragma unroll
    for (int j = 0; j < 8; j++) {
        float v = W[(size_t)k * DDIM + lane + 32 * j];
        p = __fmaf_rn(v, v, p);
    }
    #pragma unroll
    for (int o = 16; o > 0; o >>= 1)
        p = __fadd_rn(p, __shfl_down_sync(0xffffffffu, p, o));
    if (lane == 0) {
        g_ne[k] = p;
        g_halfnorm[k] = 0.5f * p;
        g_invnorm[k] = 1.0f / fmaxf(sqrtf(p), 1e-12f);
    }
    // packed fp16 W
    #pragma unroll
    for (int t = 0; t < 4; t++) {
        int w = lane + 32 * t;
        float2 v = *(const float2*)(W + (size_t)k * DDIM + 2 * w);
        g_Whx[k * 128 + w] = pack_h16x2(v.x, v.y);
    }
}

// stats init (3rd launch slot so vq_main_mma profiles as the 4th)
__global__ void vq_init0() {
    int t = threadIdx.x;
    if (t < KCODES) g_hist[t] = 0;
    if (t == 0) { g_commit = 0.0; g_div = 0.0; g_nflag = 0; }
}

// ---------------- mma.sync fp16 single-term GEMM + top-2 (ldmatrix, 3 CTA/SM) ----------------
// 64-row CTA, CN=64 code chunks single-buffered via cp.async from packed W.
// 8 warps: 2(M bands of 32 rows) x 4(N bands of 16 codes); warp tile
// 32x16 = 2 m16 x 2 n8. ~72.4 KB smem -> 3 CTAs/SM.
__global__ void __launch_bounds__(256, 3) vq_main_mma(const float* __restrict__ X)
{
    extern __shared__ __align__(16) uint32_t sm[];
    float*    hn = (float*)sm;               // [1024]
    uint32_t* xh = sm + 1024;                // [64][SSTR]
    uint32_t* wh = xh + BM * SSTR;           // [CN][SSTR]
    unsigned long long* pk = (unsigned long long*)(wh + BUFW);  // [64]
    unsigned* pk2 = (unsigned*)(pk + BM);                       // [64]

    const int tid  = threadIdx.x;
    const int lane = tid & 31;
    const int wid  = tid >> 5;
    const int wm   = wid >> 2;     // 0..1 : 32-row band
    const int wn   = wid & 3;      // 0..3 : 16-code band
    const int q    = lane >> 2;    // 0..7
    const int cg   = lane & 3;     // 0..3
    const int row0 = blockIdx.x * BM;

    const uint32_t whu = smem_u32(wh);
    const uint32_t xhu = smem_u32(xh);

    // async copy of W chunk c (CN codes x 256 dims fp16 = 32 KB)
    auto copy_chunk = [&](int c) {
        int code0 = c * CN;
        #pragma unroll
        for (int i = tid; i < CN * 32; i += 256) {
            int r = i >> 5, f4 = i & 31;
            uint32_t doff = (uint32_t)(r * SSTR + f4 * 4) * 4;
            uint32_t goff = (uint32_t)(code0 + r) * 128 + f4 * 4;
            cpa16(whu + doff, &g_Whx[goff]);
        }
    };

    copy_chunk(0); cpa_commit();   // overlap with X conversion below

    for (int i = tid; i < KCODES; i += 256) hn[i] = g_halfnorm[i];
    if (tid < BM) { pk[tid] = 0ull; pk2[tid] = 0u; }

    // X tile: fp32 -> fp16, padded layout
    for (int i = tid; i < BM * 128; i += 256) {
        int r = i >> 7, w = i & 127;
        float2 v = *(const float2*)(X + (size_t)(row0 + r) * DDIM + 2 * w);
        xh[r * SSTR + w] = pack_h16x2(v.x, v.y);
    }

    // ldmatrix per-lane base addresses (bytes)
    uint32_t a_addr[2];
    #pragma unroll
    for (int t = 0; t < 2; t++)
        a_addr[t] = xhu + (((wm * 32 + t * 16 + (lane & 15)) * SSTR + 4 * (lane >> 4)) << 2);
    const uint32_t b_base = whu + (((wn * 16 + 8 * (lane >> 4) + (lane & 7)) * SSTR
                                   + 4 * ((lane >> 3) & 1)) << 2);

    float s1[4], s2[4];
    int   i1[4];
    #pragma unroll
    for (int s = 0; s < 4; s++) { s1[s] = -1e30f; s2[s] = -1e30f; i1[s] = 0; }

    for (int nc = 0; nc < KCODES / CN; nc++) {
        cpa_wait0();         // chunk nc arrived
        __syncthreads();     // visible to all threads (covers X tile on nc=0)

        float acc[2][2][4];  // [m-tile][n-tile]
        #pragma unroll
        for (int t = 0; t < 2; t++)
            #pragma unroll
            for (int u = 0; u < 2; u++)
                #pragma unroll
                for (int e = 0; e < 4; e++) acc[t][u][e] = 0.f;

        #pragma unroll 4
        for (int ks = 0; ks < 16; ks++) {
            const uint32_t koff = ks * 32;   // 8 words
            uint32_t a[2][4];
            ldsm_x4(a[0][0], a[0][1], a[0][2], a[0][3], a_addr[0] + koff);
            ldsm_x4(a[1][0], a[1][1], a[1][2], a[1][3], a_addr[1] + koff);
            uint32_t bf[2][2];
            ldsm_x4(bf[0][0], bf[0][1], bf[1][0], bf[1][1], b_base + koff);
            #pragma unroll
            for (int t = 0; t < 2; t++)
                #pragma unroll
                for (int u = 0; u < 2; u++)
                    mma_f16(acc[t][u], a[t], bf[u]);
        }

        __syncthreads();     // all warps done reading buffer before overwrite
        if (nc < KCODES / CN - 1) copy_chunk(nc + 1);
        cpa_commit();

        // epilogue overlaps with copy flight: registers + hn only
        #pragma unroll
        for (int t = 0; t < 2; t++)
            #pragma unroll
            for (int u = 0; u < 2; u++)
                #pragma unroll
                for (int e = 0; e < 4; e++) {
                    int slot = t * 2 + (e >> 1);
                    int code = nc * CN + wn * 16 + u * 8 + cg * 2 + (e & 1);
                    float sc = acc[t][u][e] - hn[code];
                    if (sc > s1[slot]) { s2[slot] = s1[slot]; s1[slot] = sc; i1[slot] = code; }
                    else if (sc > s2[slot]) s2[slot] = sc;
                }
    }
    __syncthreads();

    // tournament 1: per-row best (first-index tiebreak)
    #pragma unroll
    for (int s = 0; s < 4; s++) {
        int rowl = wm * 32 + s * 8 + q;
        unsigned long long p = ((unsigned long long)f2o(s1[s]) << 32) |
                               (unsigned long long)(KCODES - 1 - i1[s]);
        atomicMax(&pk[rowl], p);
    }
    __syncthreads();
    // tournament 2: per-row second-best (exclude winner's code)
    #pragma unroll
    for (int s = 0; s < 4; s++) {
        int rowl = wm * 32 + s * 8 + q;
        int winner = (KCODES - 1) - (int)(pk[rowl] & 0xffffffffu);
        float cand = (i1[s] == winner) ? s2[s] : s1[s];
        atomicMax(&pk2[rowl], f2o(cand));
    }
    __syncthreads();

    if (tid < BM) {
        unsigned long long p = pk[tid];
        int idx = (KCODES - 1) - (int)(p & 0xffffffffu);
        float b1 = o2f((unsigned)(p >> 32));
        float b2 = o2f(pk2[tid]);
        int row = row0 + tid;
        g_idx[row] = idx;
        if (b1 - b2 < GAP_T) {
            g_best[row] = 0xFFFFFFFFFFFFFFFFull;
            int pos = atomicAdd(&g_nflag, 1);
            g_flagrows[pos] = row;
        }
    }
}

// ---------------- rescan v3: 8-row batched, bit-exact (validated R10) ----------------
__global__ void __launch_bounds__(256) vq_rescan3(const float* __restrict__ X) {
    __shared__ float xs[8][DDIM];
    __shared__ float nxs[8];
    __shared__ int   rws[8];
    const int tid = threadIdx.x;
    int n = g_nflag;
    if (n > NROWS) n = NROWS;
    if (n == 0) return;
    int nu = ((n + 7) >> 3) * 2;

    for (int u = blockIdx.x; u < nu; u += gridDim.x) {
        int g = u >> 1, h = u & 1;
        __syncthreads();   // protect previous iteration's xs/nxs
        if (tid < 8) {
            int s = g * 8 + tid;
            rws[tid] = g_flagrows[s < n ? s : n - 1];
        }
        __syncthreads();
        for (int i = tid; i < 8 * 64; i += 256) {
            int r = i >> 6, f = i & 63;
            *(float4*)&xs[r][f * 4] = *(const float4*)(X + (size_t)rws[r] * DDIM + f * 4);
        }
        __syncthreads();
        {   // emulated nx per row (warp w -> row w)
            int w = tid >> 5, lane = tid & 31;
            float p = 0.f;
            #pragma unroll
            for (int j = 0; j < 8; j++) {
                float v = xs[w][lane + 32 * j];
                p = __fmaf_rn(v, v, p);
            }
            #pragma unroll
            for (int o = 16; o > 0; o >>= 1)
                p = __fadd_rn(p, __shfl_down_sync(0xffffffffu, p, o));
            if (lane == 0) nxs[w] = p;
        }
        __syncthreads();

        const int k0 = h * 512 + tid;
        float a[8][2];
        #pragma unroll
        for (int r = 0; r < 8; r++) { a[r][0] = 0.f; a[r][1] = 0.f; }
        const float* w0 = g_Wt + k0;
        #pragma unroll 8
        for (int j = 0; j < DDIM; j++) {
            float wv0 = w0[(size_t)j * KCODES];
            float wv1 = w0[(size_t)j * KCODES + 256];
            #pragma unroll
            for (int r = 0; r < 8; r++) {
                float x = xs[r][j];
                a[r][0] = __fmaf_rn(x, wv0, a[r][0]);
                a[r][1] = __fmaf_rn(x, wv1, a[r][1]);
            }
        }
        float ne0 = g_ne[k0], ne1 = g_ne[k0 + 256];
        #pragma unroll
        for (int r = 0; r < 8; r++) {
            float d0 = __fadd_rn(__fmaf_rn(a[r][0], -2.0f, nxs[r]), ne0);
            float d1 = __fadd_rn(__fmaf_rn(a[r][1], -2.0f, nxs[r]), ne1);
            unsigned long long p0 = ((unsigned long long)f2o(d0) << 32) | (unsigned)k0;
            unsigned long long p1 = ((unsigned long long)f2o(d1) << 32) | (unsigned)(k0 + 256);
            atomicMin(&g_best[rws[r]], p0 < p1 ? p0 : p1);
        }
    }
}

// write winning indices for flagged rows
__global__ void vq_fix() {
    int n = g_nflag;
    if (n > NROWS) n = NROWS;
    for (int u = blockIdx.x * blockDim.x + threadIdx.x; u < n; u += gridDim.x * blockDim.x) {
        int row = g_flagrows[u];
        g_idx[row] = (int)(g_best[row] & 0xffffffffu);
    }
}

// ---------------- gather + commitment + histogram ----------------
__global__ void __launch_bounds__(256) vq_gather(
    const float* __restrict__ X, const float* __restrict__ W,
    float* __restrict__ outq, float* __restrict__ out_idx)
{
    __shared__ double cred[8];
    const int tid = threadIdx.x;
    const int row0 = blockIdx.x * 64;
    const int r  = tid >> 2;
    const int dq = tid & 3;
    const int row = row0 + r;

    int idx = g_idx[row];
    const float* erow = W + (size_t)idx * DDIM;
    const float* xrow = X + (size_t)row * DDIM;
    float* orow = outq + (size_t)row * DDIM;
    double csum = 0.0;
    #pragma unroll
    for (int j = 0; j < 16; j++) {
        int f4 = dq + 4 * j;
        float4 e4 = *(const float4*)(erow + 4 * f4);
        float4 x4 = *(const float4*)(xrow + 4 * f4);
        *(float4*)(orow + 4 * f4) = e4;
        float d0 = e4.x - x4.x;
        float d1 = e4.y - x4.y;
        float d2 = e4.z - x4.z;
        float d3 = e4.w - x4.w;
        csum += (double)d0 * d0 + (double)d1 * d1 + (double)d2 * d2 + (double)d3 * d3;
    }
    if (dq == 0) {
        atomicAdd(&g_hist[idx], 1);
        if (out_idx) out_idx[row] = (float)idx;
    }

    #pragma unroll
    for (int o = 16; o > 0; o >>= 1)
        csum += __shfl_xor_sync(0xffffffffu, csum, o);
    if ((tid & 31) == 0) cred[tid >> 5] = csum;
    __syncthreads();
    if (tid < 8) {
        double v = cred[tid];
        #pragma unroll
        for (int o = 4; o > 0; o >>= 1) v += __shfl_xor_sync(0xffu, v, o);
        if (tid == 0) atomicAdd(&g_commit, v);
    }
}

// ---------------- diversity loss ----------------
__global__ void __launch_bounds__(256) vq_div(const float* __restrict__ W) {
    __shared__ float si[32][68];
    __shared__ float sj[32][68];
    __shared__ double red[8];
    const int tid = threadIdx.x;
    const int ibase = (blockIdx.x & 15) * 64;
    const int jbase = (blockIdx.x >> 4) * 64;
    const int ig = tid & 15;
    const int jg = tid >> 4;

    float acc[4][4];
    #pragma unroll
    for (int i = 0; i < 4; i++)
        #pragma unroll
        for (int j = 0; j < 4; j++) acc[i][j] = 0.f;

    for (int dc = 0; dc < DDIM / 32; ++dc) {
        __syncthreads();
        #pragma unroll
        for (int t = 0; t < 2; t++) {
            int slot = tid + 256 * t;
            int c  = slot >> 3;
            int f4 = slot & 7;
            float4 v = *(const float4*)(W + (size_t)(ibase + c) * DDIM + dc * 32 + f4 * 4);
            float4 w = *(const float4*)(W + (size_t)(jbase + c) * DDIM + dc * 32 + f4 * 4);
            int d = f4 * 4;
            si[d + 0][c] = v.x; si[d + 1][c] = v.y; si[d + 2][c] = v.z; si[d + 3][c] = v.w;
            sj[d + 0][c] = w.x; sj[d + 1][c] = w.y; sj[d + 2][c] = w.z; sj[d + 3][c] = w.w;
        }
        __syncthreads();
        #pragma unroll
        for (int d = 0; d < 32; ++d) {
            float a[4], b[4];
            #pragma unroll
            for (int i = 0; i < 4; i++) a[i] = si[d][ig * 4 + i];
            #pragma unroll
            for (int j = 0; j < 4; j++) b[j] = sj[d][jg * 4 + j];
            #pragma unroll
            for (int i = 0; i < 4; i++)
                #pragma unroll
                for (int j = 0; j < 4; j++)
                    acc[i][j] = fmaf(a[i], b[j], acc[i][j]);
        }
    }

    float invi[4], invj[4];
    #pragma unroll
    for (int i = 0; i < 4; i++) invi[i] = g_invnorm[ibase + ig * 4 + i];
    #pragma unroll
    for (int j = 0; j < 4; j++) invj[j] = g_invnorm[jbase + jg * 4 + j];

    double s = 0.0;
    #pragma unroll
    for (int i = 0; i < 4; i++)
        #pragma unroll
        for (int j = 0; j < 4; j++) {
            float v = acc[i][j] * invi[i] * invj[j];
            if (ibase + ig * 4 + i == jbase + jg * 4 + j) v -= 1.0f;
            float t = fmaxf(fabsf(v), 0.1f);
            s += (double)t * (double)t;
        }

    #pragma unroll
    for (int o = 16; o > 0; o >>= 1) s += __shfl_xor_sync(0xffffffffu, s, o);
    if ((tid & 31) == 0) red[tid >> 5] = s;
    __syncthreads();
    if (tid < 8) {
        double v = red[tid];
        #pragma unroll
        for (int o = 4; o > 0; o >>= 1) v += __shfl_xor_sync(0xffu, v, o);
        if (tid == 0) atomicAdd(&g_div, v);
    }
}

// ---------------- entropy + combine ----------------
__global__ void vq_fin(float* __restrict__ out_loss) {
    __shared__ double red[32];
    int k = threadIdx.x;
    double p = (double)g_hist[k] * (1.0 / (double)NROWS);
    const double u = 1.0 / (double)KCODES;
    double term = u * (log(u) - log(p + 1e-10));
    #pragma unroll
    for (int o = 16; o > 0; o >>= 1) term += __shfl_xor_sync(0xffffffffu, term, o);
    if ((k & 31) == 0) red[k >> 5] = term;
    __syncthreads();
    if (k < 32) {
        double v = red[k];
        #pragma unroll
        for (int o = 16; o > 0; o >>= 1) v += __shfl_xor_sync(0xffffffffu, v, o);
        if (k == 0) {
            double commit = g_commit * (1.0 / ((double)NROWS * (double)DDIM));
            double divm   = g_div * (1.0 / ((double)KCODES * (double)KCODES));
            double total = 0.25 * commit + 0.5 * divm + 0.5 * v;
            if (out_loss) *out_loss = (float)total;
        }
    }
}

extern "C" void kernel_launch(void* const* d_in, const int* in_sizes, int n_in,
                              void* d_out, int out_size) {
    const float* X = (const float*)d_in[0];
    const float* W = (const float*)d_in[1];
    float* out = (float*)d_out;

    const long long Nq = (long long)NROWS * DDIM;
    float* out_loss = nullptr;
    float* out_idx  = nullptr;
    if ((long long)out_size >= Nq + 1 + NROWS) {
        out_loss = out + Nq;
        out_idx  = out + Nq + 1;
    }

    // dynamic smem: hn + X fp16 (64 rows) + W fp16 (64 codes) + tournaments (~72.4 KB)
    const int SMEM_MMA = (1024 + BM * SSTR + BUFW) * 4 + BM * 8 + BM * 4;
    cudaFuncSetAttribute(vq_main_mma, cudaFuncAttributeMaxDynamicSharedMemorySize, SMEM_MMA);

    vq_tr<<<256, 256>>>(W);          // 1
    vq_pre<<<KCODES / 8, 256>>>(W);  // 2
    vq_init0<<<1, 1024>>>();         // 3
    vq_main_mma<<<NROWS / BM, 256, SMEM_MMA>>>(X);  // 4  <- profiled slot
    vq_rescan3<<<1024, 256>>>(X);    // 5
    vq_fix<<<64, 256>>>();           // 6
    vq_gather<<<NROWS / 64, 256>>>(X, W, out, out_idx);  // 7
    vq_div<<<256, 256>>>(W);         // 8
    vq_fin<<<1, 1024>>>(out_loss);   // 9
}